// round 13
// baseline (speedup 1.0000x reference)
#include <cuda_runtime.h>

// Depth-4 path signature, C=10, L=512. ONE fused kernel, 2 chunks/batch:
//  - CTA pair (b,0)=producer chunk A [0,256), (b,1)=consumer chunk B [256,511).
//  - Both run the R10 register-packed f32x2 Chen scan (verbatim).
//  - Producer writes partial A with TRANSPOSED L4 (u64 at j*1000+p, coalesced)
//    and releases a flag. Consumer keeps partial B in regs, stashes B1/B2/B3
//    in smem, spins, merges with coalesced u64 loads of A4, stages the full
//    output in smem, and copies out with coalesced u64 stores.
// Grid = 128 CTAs < 148 SMs -> one wave, spin deadlock-free.

#define SIG_C 10
#define SIG_L 512
#define SIG_NSTEP 511
#define SIG_OUT 11110
#define SIG_MAXB 128
#define CHUNK0 256

// dynamic smem layout in floats:
//  [0, 11112)      stage  (first 3072 floats double as dxs during the scan)
//  [11112, 11128)  Bs1d (10 + pad)
//  [11128, 11228)  Bs2
//  [11228, 12228)  Bs3
#define OFF_BS1 11112
#define OFF_BS2 11128
#define OFF_BS3 11228
#define SMEM_FLOATS 12228
#define SMEM_BYTES (SMEM_FLOATS * 4)

typedef unsigned long long u64;

// partial A: [0,110) L1|L2, [110,1110) L3, [1110,11110) L4 transposed
__device__ __align__(16) float g_part[SIG_MAXB * SIG_OUT];
__device__ int g_flag[SIG_MAXB];   // zero-init; self-resetting

__device__ __forceinline__ u64 ffma2(u64 a, u64 b, u64 c) {
    u64 d; asm("fma.rn.f32x2 %0, %1, %2, %3;" : "=l"(d) : "l"(a), "l"(b), "l"(c)); return d;
}
__device__ __forceinline__ u64 fmul2(u64 a, u64 b) {
    u64 d; asm("mul.rn.f32x2 %0, %1, %2;" : "=l"(d) : "l"(a), "l"(b)); return d;
}
__device__ __forceinline__ u64 fadd2(u64 a, u64 b) {
    u64 d; asm("add.rn.f32x2 %0, %1, %2;" : "=l"(d) : "l"(a), "l"(b)); return d;
}
__device__ __forceinline__ u64 pack2(float lo, float hi) {
    u64 d; asm("mov.b64 %0, {%1, %2};" : "=l"(d) : "f"(lo), "f"(hi)); return d;
}
__device__ __forceinline__ void unpack2(u64 a, float& lo, float& hi) {
    asm("mov.b64 {%0, %1}, %2;" : "=f"(lo), "=f"(hi) : "l"(a));
}

__global__ __launch_bounds__(512, 1)
void sig_fused_kernel(const float* __restrict__ path, float* __restrict__ out) {
    extern __shared__ __align__(16) float sm[];
    float* dxs   = sm;              // [0, 3072) during scan
    float* stage = sm;              // [0, 11112) after scan (consumer only)
    float* Bs1d  = sm + OFF_BS1;
    float* Bs2   = sm + OFF_BS2;
    float* Bs3   = sm + OFF_BS3;

    const int b = blockIdx.x >> 1;
    const int c = blockIdx.x & 1;
    const int start = c ? CHUNK0 : 0;
    const int n = c ? (SIG_NSTEP - CHUNK0) : CHUNK0;   // consumer 255 : producer 256
    const int tid = threadIdx.x;
    const float* prow = path + (size_t)b * SIG_L * SIG_C + (size_t)start * SIG_C;

    for (int i = tid; i < n * SIG_C; i += 512) {
        int t = i / SIG_C;
        int cc = i - t * SIG_C;
        dxs[t * 12 + cc] = prow[(t + 1) * SIG_C + cc] - prow[t * SIG_C + cc];
    }
    __syncthreads();

    const bool active = (tid < 500);
    const int i1 = (tid / 100) % 5;
    const int i2 = (tid / 10) % 10;
    const int i3 = tid % 10;

    const u64 c1_2  = pack2(0.5f, 0.5f);
    const u64 c1_6  = pack2(1.0f / 6.0f, 1.0f / 6.0f);
    const u64 c1_24 = pack2(1.0f / 24.0f, 1.0f / 24.0f);

    u64 l1v2 = 0, l2v2 = 0, l3_2 = 0;
    u64 l4lo[5], l4hi[5];
#pragma unroll
    for (int j = 0; j < 5; ++j) { l4lo[j] = 0; l4hi[j] = 0; }

    if (active) {
        // ---- init with exp(dx_0) ----  (R10 verbatim)
        {
            float Bv = dxs[i2], Cv = dxs[i3];
            u64 A2 = pack2(dxs[i1], dxs[i1 + 5]);
            float d23 = Bv * Cv;
            u64 d23_2 = pack2(d23, d23);
            u64 B2 = pack2(Bv, Bv);
            l1v2 = A2;
            l2v2 = fmul2(fmul2(A2, B2), c1_2);
            l3_2 = fmul2(fmul2(A2, d23_2), c1_6);
            u64 c4 = fmul2(l3_2, pack2(0.25f, 0.25f));
            float clo, chi; unpack2(c4, clo, chi);
            u64 clo2 = pack2(clo, clo), chi2 = pack2(chi, chi);
            ulonglong2 va = *reinterpret_cast<const ulonglong2*>(dxs);
            ulonglong2 vb = *reinterpret_cast<const ulonglong2*>(dxs + 4);
            u64 vc = *reinterpret_cast<const u64*>(dxs + 8);
            l4lo[0] = fmul2(clo2, va.x); l4hi[0] = fmul2(chi2, va.x);
            l4lo[1] = fmul2(clo2, va.y); l4hi[1] = fmul2(chi2, va.y);
            l4lo[2] = fmul2(clo2, vb.x); l4hi[2] = fmul2(chi2, vb.x);
            l4lo[3] = fmul2(clo2, vb.y); l4hi[3] = fmul2(chi2, vb.y);
            l4lo[4] = fmul2(clo2, vc);   l4hi[4] = fmul2(chi2, vc);
        }

        // ---- barrier-free packed scan ----  (R10 verbatim)
        const float* q1 = dxs + i1 + 12;
        const float* q2 = dxs + i2 + 12;
        const float* q3 = dxs + i3 + 12;
        const char*  qv = reinterpret_cast<const char*>(dxs) + 48;

#pragma unroll 4
        for (int t = 1; t < n; ++t) {
            float A_lo = *q1;
            float A_hi = q1[5];
            float Bv = *q2;
            float Cv = *q3;
            ulonglong2 va = *reinterpret_cast<const ulonglong2*>(qv);
            ulonglong2 vb = *reinterpret_cast<const ulonglong2*>(qv + 16);
            u64 vc = *reinterpret_cast<const u64*>(qv + 32);
            q1 += 12; q2 += 12; q3 += 12; qv += 48;

            float d23 = Bv * Cv;
            u64 A2 = pack2(A_lo, A_hi);
            u64 d23_2 = pack2(d23, d23);
            u64 C2 = pack2(Cv, Cv);
            u64 B2 = pack2(Bv, Bv);
            u64 t1 = fmul2(A2, d23_2);
            u64 uu = fmul2(l2v2, C2);
            u64 vv = fmul2(l1v2, d23_2);
            u64 coef = ffma2(c1_24, t1, ffma2(c1_2, uu, ffma2(c1_6, vv, l3_2)));
            l3_2 = ffma2(c1_6, t1, ffma2(c1_2, vv, fadd2(l3_2, uu)));
            l2v2 = ffma2(ffma2(c1_2, A2, l1v2), B2, l2v2);
            l1v2 = fadd2(l1v2, A2);

            float clo, chi; unpack2(coef, clo, chi);
            u64 clo2 = pack2(clo, clo), chi2 = pack2(chi, chi);
            l4lo[0] = ffma2(clo2, va.x, l4lo[0]); l4hi[0] = ffma2(chi2, va.x, l4hi[0]);
            l4lo[1] = ffma2(clo2, va.y, l4lo[1]); l4hi[1] = ffma2(chi2, va.y, l4hi[1]);
            l4lo[2] = ffma2(clo2, vb.x, l4lo[2]); l4hi[2] = ffma2(chi2, vb.x, l4hi[2]);
            l4lo[3] = ffma2(clo2, vb.y, l4lo[3]); l4hi[3] = ffma2(chi2, vb.y, l4hi[3]);
            l4lo[4] = ffma2(clo2, vc,   l4lo[4]); l4hi[4] = ffma2(chi2, vc,   l4hi[4]);
        }
    }

    float lo, hi;

    if (c == 0) {
        // ---- producer: write partial A (L4 transposed, coalesced), flag ----
        float* dst = g_part + (size_t)b * SIG_OUT;
        if (active) {
            if (i2 == 0 && i3 == 0) {
                unpack2(l1v2, lo, hi);
                dst[i1] = lo; dst[i1 + 5] = hi;
            }
            if (i3 == 0) {
                unpack2(l2v2, lo, hi);
                dst[10 + i1 * 10 + i2] = lo;
                dst[10 + (i1 + 5) * 10 + i2] = hi;
            }
            unpack2(l3_2, lo, hi);
            dst[110 + tid] = lo;
            dst[110 + tid + 500] = hi;
            u64* d4 = reinterpret_cast<u64*>(dst + 1110);
#pragma unroll
            for (int j = 0; j < 5; ++j) {
                d4[j * 1000 + tid]       = l4lo[j];
                d4[j * 1000 + tid + 500] = l4hi[j];
            }
        }
        __threadfence();
        __syncthreads();
        if (tid == 0) {
            asm volatile("st.release.gpu.global.b32 [%0], %1;"
                         :: "l"(g_flag + b), "r"(1) : "memory");
        }
        return;
    }

    // ---- consumer: stash B levels 1-3 in smem tables ----
    float b3lo = 0.0f, b3hi = 0.0f;
    if (active) {
        if (i2 == 0 && i3 == 0) {
            unpack2(l1v2, lo, hi);
            Bs1d[i1] = lo; Bs1d[i1 + 5] = hi;
        }
        if (i3 == 0) {
            unpack2(l2v2, lo, hi);
            Bs2[i1 * 10 + i2] = lo;
            Bs2[(i1 + 5) * 10 + i2] = hi;
        }
        unpack2(l3_2, b3lo, b3hi);
        Bs3[tid] = b3lo;
        Bs3[tid + 500] = b3hi;
    }
    if (tid >= 500 && tid < 506) Bs1d[tid - 500 + 10] = 0.0f;   // pad for u64 reads
    __syncthreads();

    // ---- spin on producer flag, reset for graph replay ----
    if (tid == 0) {
        unsigned f;
        do {
            asm volatile("ld.acquire.gpu.global.b32 %0, [%1];"
                         : "=r"(f) : "l"(g_flag + b) : "memory");
        } while (f == 0);
        asm volatile("st.relaxed.gpu.global.b32 [%0], %1;"
                     :: "l"(g_flag + b), "r"(0) : "memory");
    }
    __syncthreads();

    // ---- merge A (global, coalesced) (x) B (regs/smem) into stage ----
    const float* a = g_part + (size_t)b * SIG_OUT;
    if (active) {
        // coalesced u64 loads of A4, issued up front
        const u64* A4 = reinterpret_cast<const u64*>(a + 1110);
        u64 a4lo[5], a4hi[5];
#pragma unroll
        for (int j = 0; j < 5; ++j) a4lo[j] = A4[j * 1000 + tid];
#pragma unroll
        for (int j = 0; j < 5; ++j) a4hi[j] = A4[j * 1000 + tid + 500];
        float a3lo = a[110 + tid];
        float a3hi = a[110 + tid + 500];
        float a1lo = a[i1], a1hi = a[i1 + 5];
        float a2lo = a[10 + i1 * 10 + i2], a2hi = a[10 + (i1 + 5) * 10 + i2];

        // level 3
        float b1s = Bs1d[i3];
        float b2s = Bs2[i2 * 10 + i3];
        stage[110 + tid]       = a3lo + b3lo + a2lo * b1s + a1lo * b2s;
        stage[110 + tid + 500] = a3hi + b3hi + a2hi * b1s + a1hi * b2s;

        // level 4
        const u64* B1q = reinterpret_cast<const u64*>(Bs1d);
        const u64* B2q = reinterpret_cast<const u64*>(Bs2 + i3 * 10);
        const u64* B3q = reinterpret_cast<const u64*>(Bs3 + i2 * 100 + i3 * 10);
        u64 a3lo2 = pack2(a3lo, a3lo), a3hi2 = pack2(a3hi, a3hi);
        u64 a2lo2 = pack2(a2lo, a2lo), a2hi2 = pack2(a2hi, a2hi);
        u64 a1lo2 = pack2(a1lo, a1lo), a1hi2 = pack2(a1hi, a1hi);
        u64* s4lo = reinterpret_cast<u64*>(stage + 1110) + (size_t)tid * 5;
        u64* s4hi = reinterpret_cast<u64*>(stage + 1110) + (size_t)(tid + 500) * 5;
#pragma unroll
        for (int j = 0; j < 5; ++j) {
            u64 s = fadd2(l4lo[j], a4lo[j]);
            s = ffma2(a3lo2, B1q[j], s);
            s = ffma2(a2lo2, B2q[j], s);
            s = ffma2(a1lo2, B3q[j], s);
            s4lo[j] = s;
            u64 t2 = fadd2(l4hi[j], a4hi[j]);
            t2 = ffma2(a3hi2, B1q[j], t2);
            t2 = ffma2(a2hi2, B2q[j], t2);
            t2 = ffma2(a1hi2, B3q[j], t2);
            s4hi[j] = t2;
        }
    }
    // head (levels 1+2): threads 0..109 double-duty
    if (tid < 110) {
        if (tid < 10) {
            stage[tid] = a[tid] + Bs1d[tid];
        } else {
            int m = tid - 10;
            stage[tid] = a[10 + m] + Bs2[m] + a[m / 10] * Bs1d[m % 10];
        }
    }
    __syncthreads();

    // ---- coalesced u64 copy: stage -> out ----
    const u64* sp = reinterpret_cast<const u64*>(stage);
    u64* op = reinterpret_cast<u64*>(out + (size_t)b * SIG_OUT);
    for (int i = tid; i < SIG_OUT / 2; i += 512) op[i] = sp[i];
}

extern "C" void kernel_launch(void* const* d_in, const int* in_sizes, int n_in,
                              void* d_out, int out_size) {
    const float* path = (const float*)d_in[0];
    float* out = (float*)d_out;
    int B = in_sizes[0] / (SIG_L * SIG_C);
    if (B > SIG_MAXB) B = SIG_MAXB;
    cudaFuncSetAttribute(sig_fused_kernel,
                         cudaFuncAttributeMaxDynamicSharedMemorySize, SMEM_BYTES);
    sig_fused_kernel<<<B * 2, 512, SMEM_BYTES>>>(path, out);
}

// round 14
// speedup vs baseline: 1.0107x; 1.0107x over previous
#include <cuda_runtime.h>

// Depth-4 path signature, C=10, L=512. ONE fused kernel, 2 chunks/batch:
//  - CTA pair (b,0)=producer chunk A [0,256), (b,1)=consumer chunk B [256,511).
//  - Both run the R10 register-packed f32x2 Chen scan (verbatim).
//  - Producer writes partial A with TRANSPOSED L4 (u64 at j*1000+p, coalesced)
//    and releases a flag. Consumer keeps partial B in regs, stashes B1/B2/B3
//    in smem, spins, merges with coalesced u64 loads of A4, stages the full
//    output in smem, and copies out with coalesced u64 stores.
// Grid = 128 CTAs < 148 SMs -> one wave, spin deadlock-free.

#define SIG_C 10
#define SIG_L 512
#define SIG_NSTEP 511
#define SIG_OUT 11110
#define SIG_MAXB 128
#define CHUNK0 256

// dynamic smem layout in floats:
//  [0, 11112)      stage  (first 3072 floats double as dxs during the scan)
//  [11112, 11128)  Bs1d (10 + pad)
//  [11128, 11228)  Bs2
//  [11228, 12228)  Bs3
#define OFF_BS1 11112
#define OFF_BS2 11128
#define OFF_BS3 11228
#define SMEM_FLOATS 12228
#define SMEM_BYTES (SMEM_FLOATS * 4)

typedef unsigned long long u64;

// partial A: [0,110) L1|L2, [110,1110) L3, [1110,11110) L4 transposed
__device__ __align__(16) float g_part[SIG_MAXB * SIG_OUT];
__device__ int g_flag[SIG_MAXB];   // zero-init; self-resetting

__device__ __forceinline__ u64 ffma2(u64 a, u64 b, u64 c) {
    u64 d; asm("fma.rn.f32x2 %0, %1, %2, %3;" : "=l"(d) : "l"(a), "l"(b), "l"(c)); return d;
}
__device__ __forceinline__ u64 fmul2(u64 a, u64 b) {
    u64 d; asm("mul.rn.f32x2 %0, %1, %2;" : "=l"(d) : "l"(a), "l"(b)); return d;
}
__device__ __forceinline__ u64 fadd2(u64 a, u64 b) {
    u64 d; asm("add.rn.f32x2 %0, %1, %2;" : "=l"(d) : "l"(a), "l"(b)); return d;
}
__device__ __forceinline__ u64 pack2(float lo, float hi) {
    u64 d; asm("mov.b64 %0, {%1, %2};" : "=l"(d) : "f"(lo), "f"(hi)); return d;
}
__device__ __forceinline__ void unpack2(u64 a, float& lo, float& hi) {
    asm("mov.b64 {%0, %1}, %2;" : "=f"(lo), "=f"(hi) : "l"(a));
}

__global__ __launch_bounds__(512, 1)
void sig_fused_kernel(const float* __restrict__ path, float* __restrict__ out) {
    extern __shared__ __align__(16) float sm[];
    float* dxs   = sm;              // [0, 3072) during scan
    float* stage = sm;              // [0, 11112) after scan (consumer only)
    float* Bs1d  = sm + OFF_BS1;
    float* Bs2   = sm + OFF_BS2;
    float* Bs3   = sm + OFF_BS3;

    const int b = blockIdx.x >> 1;
    const int c = blockIdx.x & 1;
    const int start = c ? CHUNK0 : 0;
    const int n = c ? (SIG_NSTEP - CHUNK0) : CHUNK0;   // consumer 255 : producer 256
    const int tid = threadIdx.x;
    const float* prow = path + (size_t)b * SIG_L * SIG_C + (size_t)start * SIG_C;

    for (int i = tid; i < n * SIG_C; i += 512) {
        int t = i / SIG_C;
        int cc = i - t * SIG_C;
        dxs[t * 12 + cc] = prow[(t + 1) * SIG_C + cc] - prow[t * SIG_C + cc];
    }
    __syncthreads();

    const bool active = (tid < 500);
    const int i1 = (tid / 100) % 5;
    const int i2 = (tid / 10) % 10;
    const int i3 = tid % 10;

    const u64 c1_2  = pack2(0.5f, 0.5f);
    const u64 c1_6  = pack2(1.0f / 6.0f, 1.0f / 6.0f);
    const u64 c1_24 = pack2(1.0f / 24.0f, 1.0f / 24.0f);

    u64 l1v2 = 0, l2v2 = 0, l3_2 = 0;
    u64 l4lo[5], l4hi[5];
#pragma unroll
    for (int j = 0; j < 5; ++j) { l4lo[j] = 0; l4hi[j] = 0; }

    if (active) {
        // ---- init with exp(dx_0) ----  (R10 verbatim)
        {
            float Bv = dxs[i2], Cv = dxs[i3];
            u64 A2 = pack2(dxs[i1], dxs[i1 + 5]);
            float d23 = Bv * Cv;
            u64 d23_2 = pack2(d23, d23);
            u64 B2 = pack2(Bv, Bv);
            l1v2 = A2;
            l2v2 = fmul2(fmul2(A2, B2), c1_2);
            l3_2 = fmul2(fmul2(A2, d23_2), c1_6);
            u64 c4 = fmul2(l3_2, pack2(0.25f, 0.25f));
            float clo, chi; unpack2(c4, clo, chi);
            u64 clo2 = pack2(clo, clo), chi2 = pack2(chi, chi);
            ulonglong2 va = *reinterpret_cast<const ulonglong2*>(dxs);
            ulonglong2 vb = *reinterpret_cast<const ulonglong2*>(dxs + 4);
            u64 vc = *reinterpret_cast<const u64*>(dxs + 8);
            l4lo[0] = fmul2(clo2, va.x); l4hi[0] = fmul2(chi2, va.x);
            l4lo[1] = fmul2(clo2, va.y); l4hi[1] = fmul2(chi2, va.y);
            l4lo[2] = fmul2(clo2, vb.x); l4hi[2] = fmul2(chi2, vb.x);
            l4lo[3] = fmul2(clo2, vb.y); l4hi[3] = fmul2(chi2, vb.y);
            l4lo[4] = fmul2(clo2, vc);   l4hi[4] = fmul2(chi2, vc);
        }

        // ---- barrier-free packed scan ----  (R10 verbatim)
        const float* q1 = dxs + i1 + 12;
        const float* q2 = dxs + i2 + 12;
        const float* q3 = dxs + i3 + 12;
        const char*  qv = reinterpret_cast<const char*>(dxs) + 48;

#pragma unroll 4
        for (int t = 1; t < n; ++t) {
            float A_lo = *q1;
            float A_hi = q1[5];
            float Bv = *q2;
            float Cv = *q3;
            ulonglong2 va = *reinterpret_cast<const ulonglong2*>(qv);
            ulonglong2 vb = *reinterpret_cast<const ulonglong2*>(qv + 16);
            u64 vc = *reinterpret_cast<const u64*>(qv + 32);
            q1 += 12; q2 += 12; q3 += 12; qv += 48;

            float d23 = Bv * Cv;
            u64 A2 = pack2(A_lo, A_hi);
            u64 d23_2 = pack2(d23, d23);
            u64 C2 = pack2(Cv, Cv);
            u64 B2 = pack2(Bv, Bv);
            u64 t1 = fmul2(A2, d23_2);
            u64 uu = fmul2(l2v2, C2);
            u64 vv = fmul2(l1v2, d23_2);
            u64 coef = ffma2(c1_24, t1, ffma2(c1_2, uu, ffma2(c1_6, vv, l3_2)));
            l3_2 = ffma2(c1_6, t1, ffma2(c1_2, vv, fadd2(l3_2, uu)));
            l2v2 = ffma2(ffma2(c1_2, A2, l1v2), B2, l2v2);
            l1v2 = fadd2(l1v2, A2);

            float clo, chi; unpack2(coef, clo, chi);
            u64 clo2 = pack2(clo, clo), chi2 = pack2(chi, chi);
            l4lo[0] = ffma2(clo2, va.x, l4lo[0]); l4hi[0] = ffma2(chi2, va.x, l4hi[0]);
            l4lo[1] = ffma2(clo2, va.y, l4lo[1]); l4hi[1] = ffma2(chi2, va.y, l4hi[1]);
            l4lo[2] = ffma2(clo2, vb.x, l4lo[2]); l4hi[2] = ffma2(chi2, vb.x, l4hi[2]);
            l4lo[3] = ffma2(clo2, vb.y, l4lo[3]); l4hi[3] = ffma2(chi2, vb.y, l4hi[3]);
            l4lo[4] = ffma2(clo2, vc,   l4lo[4]); l4hi[4] = ffma2(chi2, vc,   l4hi[4]);
        }
    }

    float lo, hi;

    if (c == 0) {
        // ---- producer: write partial A (L4 transposed, coalesced), flag ----
        float* dst = g_part + (size_t)b * SIG_OUT;
        if (active) {
            if (i2 == 0 && i3 == 0) {
                unpack2(l1v2, lo, hi);
                dst[i1] = lo; dst[i1 + 5] = hi;
            }
            if (i3 == 0) {
                unpack2(l2v2, lo, hi);
                dst[10 + i1 * 10 + i2] = lo;
                dst[10 + (i1 + 5) * 10 + i2] = hi;
            }
            unpack2(l3_2, lo, hi);
            dst[110 + tid] = lo;
            dst[110 + tid + 500] = hi;
            u64* d4 = reinterpret_cast<u64*>(dst + 1110);
#pragma unroll
            for (int j = 0; j < 5; ++j) {
                d4[j * 1000 + tid]       = l4lo[j];
                d4[j * 1000 + tid + 500] = l4hi[j];
            }
        }
        __threadfence();
        __syncthreads();
        if (tid == 0) {
            asm volatile("st.release.gpu.global.b32 [%0], %1;"
                         :: "l"(g_flag + b), "r"(1) : "memory");
        }
        return;
    }

    // ---- consumer: stash B levels 1-3 in smem tables ----
    float b3lo = 0.0f, b3hi = 0.0f;
    if (active) {
        if (i2 == 0 && i3 == 0) {
            unpack2(l1v2, lo, hi);
            Bs1d[i1] = lo; Bs1d[i1 + 5] = hi;
        }
        if (i3 == 0) {
            unpack2(l2v2, lo, hi);
            Bs2[i1 * 10 + i2] = lo;
            Bs2[(i1 + 5) * 10 + i2] = hi;
        }
        unpack2(l3_2, b3lo, b3hi);
        Bs3[tid] = b3lo;
        Bs3[tid + 500] = b3hi;
    }
    if (tid >= 500 && tid < 506) Bs1d[tid - 500 + 10] = 0.0f;   // pad for u64 reads
    __syncthreads();

    // ---- spin on producer flag, reset for graph replay ----
    if (tid == 0) {
        unsigned f;
        do {
            asm volatile("ld.acquire.gpu.global.b32 %0, [%1];"
                         : "=r"(f) : "l"(g_flag + b) : "memory");
        } while (f == 0);
        asm volatile("st.relaxed.gpu.global.b32 [%0], %1;"
                     :: "l"(g_flag + b), "r"(0) : "memory");
    }
    __syncthreads();

    // ---- merge A (global, coalesced) (x) B (regs/smem) into stage ----
    const float* a = g_part + (size_t)b * SIG_OUT;
    if (active) {
        // coalesced u64 loads of A4, issued up front
        const u64* A4 = reinterpret_cast<const u64*>(a + 1110);
        u64 a4lo[5], a4hi[5];
#pragma unroll
        for (int j = 0; j < 5; ++j) a4lo[j] = A4[j * 1000 + tid];
#pragma unroll
        for (int j = 0; j < 5; ++j) a4hi[j] = A4[j * 1000 + tid + 500];
        float a3lo = a[110 + tid];
        float a3hi = a[110 + tid + 500];
        float a1lo = a[i1], a1hi = a[i1 + 5];
        float a2lo = a[10 + i1 * 10 + i2], a2hi = a[10 + (i1 + 5) * 10 + i2];

        // level 3
        float b1s = Bs1d[i3];
        float b2s = Bs2[i2 * 10 + i3];
        stage[110 + tid]       = a3lo + b3lo + a2lo * b1s + a1lo * b2s;
        stage[110 + tid + 500] = a3hi + b3hi + a2hi * b1s + a1hi * b2s;

        // level 4
        const u64* B1q = reinterpret_cast<const u64*>(Bs1d);
        const u64* B2q = reinterpret_cast<const u64*>(Bs2 + i3 * 10);
        const u64* B3q = reinterpret_cast<const u64*>(Bs3 + i2 * 100 + i3 * 10);
        u64 a3lo2 = pack2(a3lo, a3lo), a3hi2 = pack2(a3hi, a3hi);
        u64 a2lo2 = pack2(a2lo, a2lo), a2hi2 = pack2(a2hi, a2hi);
        u64 a1lo2 = pack2(a1lo, a1lo), a1hi2 = pack2(a1hi, a1hi);
        u64* s4lo = reinterpret_cast<u64*>(stage + 1110) + (size_t)tid * 5;
        u64* s4hi = reinterpret_cast<u64*>(stage + 1110) + (size_t)(tid + 500) * 5;
#pragma unroll
        for (int j = 0; j < 5; ++j) {
            u64 s = fadd2(l4lo[j], a4lo[j]);
            s = ffma2(a3lo2, B1q[j], s);
            s = ffma2(a2lo2, B2q[j], s);
            s = ffma2(a1lo2, B3q[j], s);
            s4lo[j] = s;
            u64 t2 = fadd2(l4hi[j], a4hi[j]);
            t2 = ffma2(a3hi2, B1q[j], t2);
            t2 = ffma2(a2hi2, B2q[j], t2);
            t2 = ffma2(a1hi2, B3q[j], t2);
            s4hi[j] = t2;
        }
    }
    // head (levels 1+2): threads 0..109 double-duty
    if (tid < 110) {
        if (tid < 10) {
            stage[tid] = a[tid] + Bs1d[tid];
        } else {
            int m = tid - 10;
            stage[tid] = a[10 + m] + Bs2[m] + a[m / 10] * Bs1d[m % 10];
        }
    }
    __syncthreads();

    // ---- coalesced u64 copy: stage -> out ----
    const u64* sp = reinterpret_cast<const u64*>(stage);
    u64* op = reinterpret_cast<u64*>(out + (size_t)b * SIG_OUT);
    for (int i = tid; i < SIG_OUT / 2; i += 512) op[i] = sp[i];
}

extern "C" void kernel_launch(void* const* d_in, const int* in_sizes, int n_in,
                              void* d_out, int out_size) {
    const float* path = (const float*)d_in[0];
    float* out = (float*)d_out;
    int B = in_sizes[0] / (SIG_L * SIG_C);
    if (B > SIG_MAXB) B = SIG_MAXB;
    cudaFuncSetAttribute(sig_fused_kernel,
                         cudaFuncAttributeMaxDynamicSharedMemorySize, SMEM_BYTES);
    sig_fused_kernel<<<B * 2, 512, SMEM_BYTES>>>(path, out);
}